// round 14
// baseline (speedup 1.0000x reference)
#include <cuda_runtime.h>
#include <cuda_bf16.h>
#include <math.h>
#include <stdint.h>

#define B_  32
#define T_  20
#define C_  512
#define P_  196
#define H_  1024
#define NC_ 101
#define NBLK 148
#define NTHR 512
#define NWRP 16
#define KCH 128           // k elements per chunk

// SMEM byte layout: A tiles [128 m][128 k] bf16 @ stride 272 B, B tiles [32 n][128 k]
#define ASTR_B 272
#define AHI_B 0                     // 128*272 = 34816
#define ALO_B 34816
#define BHI_B 69632                 // 32*272 = 8704
#define BLO_B 78336
#define TBUF_B 87040                // per buffer
#define SMEM_BYTES (2 * TBUF_B)     // 174080

// ---------------- device scratch ----------------
__device__ float g_sA2pre[T_ * B_ * P_];
__device__ float g_tC2pre[T_ * B_ * P_];
__device__ float g_alpha[B_ * P_];
__device__ float g_h2n[B_ * H_];          // [b][h] fp32 (scores)
__device__ float g_h2hist[T_ * H_ * B_];  // [t][h][b]
__device__ float g_c1[H_ * B_];           // [h][b]
__device__ float g_c2[H_ * B_];
__device__ float g_beta[T_ * B_];
__device__ float g_betasT[B_ * T_];
__device__ float g_hbarN[B_ * H_];
__device__ unsigned g_cnt2[32 * 32];
__device__ volatile unsigned g_bar_gen;
__device__ volatile unsigned g_aflag;     // alpha-ready flag (monotonic per step)

// GEMM partials: [3 slices][32 m][128 rows * 32 b]
__device__ float g_p1[3][32 * 128 * 32];
__device__ float g_p2[3][32 * 128 * 32];

// bf16 hi/lo activations [b][k]
__device__ __nv_bfloat16 g_Yhi[B_ * C_], g_Ylo[B_ * C_];
__device__ __nv_bfloat16 g_h1hi[B_ * H_], g_h1lo[B_ * H_];
__device__ __nv_bfloat16 g_h2hi[B_ * H_], g_h2lo[B_ * H_];

// repacked (row-permuted, K-major) weights, hi/lo bf16
__device__ __nv_bfloat16 g_W1hi[4096 * 1536], g_W1lo[4096 * 1536];
__device__ __nv_bfloat16 g_W2hi[4096 * 2048], g_W2lo[4096 * 2048];

__device__ __forceinline__ float sigm(float x) { return 1.0f / (1.0f + __expf(-x)); }
__device__ __forceinline__ float ftanh(float x) { return 1.0f - 2.0f / (__expf(2.0f * x) + 1.0f); }
__device__ __forceinline__ float d4(float4 a, float4 b) {
    return a.x * b.x + a.y * b.y + a.z * b.z + a.w * b.w;
}

__device__ __forceinline__ void cp16(void* dst, const void* src) {
    unsigned u = (unsigned)__cvta_generic_to_shared(dst);
    asm volatile("cp.async.cg.shared.global [%0], [%1], 16;" :: "r"(u), "l"(src));
}
__device__ __forceinline__ void cp_commit() { asm volatile("cp.async.commit_group;" ::: "memory"); }
__device__ __forceinline__ void cp_wait1()  { asm volatile("cp.async.wait_group 1;" ::: "memory"); }
__device__ __forceinline__ void cp_wait0()  { asm volatile("cp.async.wait_group 0;" ::: "memory"); }

__device__ __forceinline__ uint32_t smem_u32(const void* p) {
    return (uint32_t)__cvta_generic_to_shared(p);
}

// ldmatrix x4 (b16)
__device__ __forceinline__ void ldsm4(uint32_t* r, uint32_t addr) {
    asm volatile("ldmatrix.sync.aligned.m8n8.x4.shared.b16 {%0,%1,%2,%3}, [%4];"
                 : "=r"(r[0]), "=r"(r[1]), "=r"(r[2]), "=r"(r[3]) : "r"(addr));
}
// HMMA m16n8k16 bf16 -> f32 accumulate
__device__ __forceinline__ void mma16816(float* d, const uint32_t* a, const uint32_t* b) {
    asm volatile(
        "mma.sync.aligned.m16n8k16.row.col.f32.bf16.bf16.f32 "
        "{%0,%1,%2,%3}, {%4,%5,%6,%7}, {%8,%9}, {%0,%1,%2,%3};"
        : "+f"(d[0]), "+f"(d[1]), "+f"(d[2]), "+f"(d[3])
        : "r"(a[0]), "r"(a[1]), "r"(a[2]), "r"(a[3]), "r"(b[0]), "r"(b[1]));
}

// distributed grid barrier (nanosleep variant — best measured)
__device__ __forceinline__ void grid_sync(unsigned& barI, unsigned gen0) {
    barI++;
    __syncthreads();
    const int tid = threadIdx.x, bid = blockIdx.x;
    if (tid == 0) { __threadfence(); atomicAdd(&g_cnt2[(bid & 31) * 32], 1u); }
    if (bid == 0 && tid < 32) {
        unsigned nj = (tid < 20) ? 5u : 4u;
        volatile unsigned* c = &g_cnt2[tid * 32];
        while (*c < nj) __nanosleep(32);
        atomicSub(&g_cnt2[tid * 32], nj);
        __syncwarp(0xffffffffu);
        if (tid == 0) { __threadfence(); g_bar_gen = gen0 + barI; }
    } else if (tid == 0) {
        while ((unsigned)(g_bar_gen - gen0) < barI) __nanosleep(32);
    }
    __threadfence();
    __syncthreads();
}

// ---------------- generic HMMA partial-GEMM tile ----------------
// Computes part[m-tile rows 0..127][32 b] over k [kbase, kbase+klen) -> gp.
// MODE 0: W=g_W1 (K=1536), X1=Y(str 512, k<512), X2=h1(str 1024)
// MODE 1: W=g_W2 (K=2048), X1=h1(str 1024, k<1024), X2=h2(str 1024)
template <int MODE>
__device__ void gemm_part(int m, int kbase, int klen, float* gp,
                          float* dsm, uint32_t smem_base) {
    constexpr int K = (MODE == 0) ? 1536 : 2048;
    constexpr int K1 = (MODE == 0) ? 512 : 1024;
    const int X1STR = (MODE == 0) ? 512 : 1024;
    const __nv_bfloat16* Whi = (MODE == 0) ? g_W1hi : g_W2hi;
    const __nv_bfloat16* Wlo = (MODE == 0) ? g_W1lo : g_W2lo;
    const __nv_bfloat16* X1hi = (MODE == 0) ? g_Yhi : g_h1hi;
    const __nv_bfloat16* X1lo = (MODE == 0) ? g_Ylo : g_h1lo;
    const __nv_bfloat16* X2hi = (MODE == 0) ? g_h1hi : g_h2hi;
    const __nv_bfloat16* X2lo = (MODE == 0) ? g_h1lo : g_h2lo;

    const int NCH = klen / KCH;
    const int tid = threadIdx.x;
    char* smem_c = (char*)dsm;

    auto load_chunk = [&](int c) {
        char* basep = smem_c + (c & 1) * TBUF_B;
        const int kc = kbase + c * KCH;
#pragma unroll
        for (int i = 0; i < 4; i++) {
            int g = tid + 512 * i;
            int row = g >> 4, gi = g & 15;
            size_t soff = (size_t)(m * 128 + row) * K + kc + gi * 8;
            cp16(basep + AHI_B + row * ASTR_B + gi * 16, Whi + soff);
            cp16(basep + ALO_B + row * ASTR_B + gi * 16, Wlo + soff);
        }
        {
            int row = tid >> 4, gi = tid & 15;
            int k = kc + gi * 8;
            const __nv_bfloat16 *shi, *slo;
            if (k < K1) { shi = X1hi + row * X1STR + k; slo = X1lo + row * X1STR + k; }
            else        { shi = X2hi + row * 1024 + (k - K1); slo = X2lo + row * 1024 + (k - K1); }
            cp16(basep + BHI_B + row * ASTR_B + gi * 16, shi);
            cp16(basep + BLO_B + row * ASTR_B + gi * 16, slo);
        }
    };

    const int w = tid >> 5, lane = tid & 31;
    const int m0 = (w & 7) * 16, n0 = (w >> 3) * 16;
    const int mi = lane >> 3, rr = lane & 7;
    const int a_m = m0 + (mi & 1) * 8 + rr, a_k = (mi >> 1) * 8;
    const int b_n = n0 + (mi >> 1) * 8 + rr, b_k = (mi & 1) * 8;

    float acc[2][4] = {{0.f, 0.f, 0.f, 0.f}, {0.f, 0.f, 0.f, 0.f}};

    load_chunk(0); cp_commit();
    if (NCH > 1) { load_chunk(1); cp_commit(); }

    for (int c = 0; c < NCH; c++) {
        if (c + 1 < NCH) cp_wait1(); else cp_wait0();
        __syncthreads();

        uint32_t tb = smem_base + (c & 1) * TBUF_B;
        uint32_t aHi = tb + AHI_B + a_m * ASTR_B + a_k * 2;
        uint32_t aLo = tb + ALO_B + a_m * ASTR_B + a_k * 2;
        uint32_t bHi = tb + BHI_B + b_n * ASTR_B + b_k * 2;
        uint32_t bLo = tb + BLO_B + b_n * ASTR_B + b_k * 2;
#pragma unroll
        for (int kk = 0; kk < 8; kk++) {
            uint32_t ah[4], al[4], bh[4], bl[4];
            ldsm4(ah, aHi + kk * 32);
            ldsm4(al, aLo + kk * 32);
            ldsm4(bh, bHi + kk * 32);
            ldsm4(bl, bLo + kk * 32);
            mma16816(acc[0], ah, bh + 0);
            mma16816(acc[1], ah, bh + 2);
            mma16816(acc[0], ah, bl + 0);
            mma16816(acc[1], ah, bl + 2);
            mma16816(acc[0], al, bh + 0);
            mma16816(acc[1], al, bh + 2);
        }
        __syncthreads();
        if (c + 2 < NCH) { load_chunk(c + 2); cp_commit(); }
    }

    {
        int gm = lane >> 2, qc = (lane & 3) * 2;
        int r1 = m0 + gm, r2 = r1 + 8;
#pragma unroll
        for (int tt = 0; tt < 2; tt++) {
            int cc = n0 + tt * 8 + qc;
            *(float2*)&gp[r1 * 32 + cc] = make_float2(acc[tt][0], acc[tt][1]);
            *(float2*)&gp[r2 * 32 + cc] = make_float2(acc[tt][2], acc[tt][3]);
        }
    }
}

// ---------------- fused cell for m = bid (3 slices) ----------------
template <int MODE>
__device__ void cell_m(int t, const float* __restrict__ bih, const float* __restrict__ bhh) {
    const int m = blockIdx.x, tid = threadIdx.x;
    float (*gp)[32 * 128 * 32] = (MODE == 0) ? g_p1 : g_p2;
    for (int idx = tid; idx < 1024; idx += NTHR) {
        int u = idx >> 5, b = idx & 31;
        int ug = m * 32 + u;
        float gate[4];
#pragma unroll
        for (int q = 0; q < 4; q++) {
            int off = m * 4096 + (q * 32 + u) * 32 + b;
            float s = bih[q * 1024 + ug] + bhh[q * 1024 + ug];
#pragma unroll
            for (int sl = 0; sl < 3; sl++) s += gp[sl][off];
            gate[q] = s;
        }
        float i_ = sigm(gate[0]), f_ = sigm(gate[1]), gv = ftanh(gate[2]), o_ = sigm(gate[3]);
        float* cS = (MODE == 0) ? g_c1 : g_c2;
        float cn = f_ * cS[ug * 32 + b] + i_ * gv;
        float hn = o_ * ftanh(cn);
        cS[ug * 32 + b] = cn;
        __nv_bfloat16 hhi = __float2bfloat16(hn);
        __nv_bfloat16 hlo = __float2bfloat16(hn - __bfloat162float(hhi));
        if (MODE == 0) {
            g_h1hi[b * 1024 + ug] = hhi;
            g_h1lo[b * 1024 + ug] = hlo;
        } else {
            g_h2hi[b * 1024 + ug] = hhi;
            g_h2lo[b * 1024 + ug] = hlo;
            g_h2n[b * 1024 + ug] = hn;
            g_h2hist[(size_t)t * H_ * B_ + ug * B_ + b] = hn;
        }
    }
}

// ---------------- per-batch attention: scores + softmax + beta + alpha ----------
__device__ void attn_b(int t, int b, float* dsm,
                       const float* __restrict__ W_h2p, const float* __restrict__ b_h2p,
                       const float* __restrict__ W_h21, const float* __restrict__ b_h21,
                       const float* __restrict__ b_tC21, const float* __restrict__ temporalBias,
                       float* __restrict__ alphas_out) {
    const int tid = threadIdx.x, lane = tid & 31, wid = tid >> 5;
    float* h2s  = dsm;           // [1024]
    float* sc   = dsm + 1024;    // [200]
    float* sred = dsm + 1232;    // [16]

    for (int i = tid; i < H_; i += NTHR) h2s[i] = g_h2n[b * H_ + i];
    __syncthreads();

    const float4* xr = (const float4*)h2s;
    for (int p = wid; p < 197; p += NWRP) {
        const float4* wr = (const float4*)((p < P_) ? (W_h2p + (size_t)p * H_) : W_h21);
        float acc = 0.f;
#pragma unroll
        for (int j = 0; j < 8; j++) acc += d4(wr[lane + 32 * j], xr[lane + 32 * j]);
        for (int o = 16; o; o >>= 1) acc += __shfl_xor_sync(~0u, acc, o);
        if (lane == 0)
            sc[p] = (p < P_) ? (acc + b_h2p[p] + g_sA2pre[(t * B_ + b) * P_ + p]) : acc;
    }
    __syncthreads();

    float v = (tid < P_) ? sc[tid] : -1e30f;
    float m = v;
    for (int o = 16; o; o >>= 1) m = fmaxf(m, __shfl_xor_sync(~0u, m, o));
    if (lane == 0) sred[wid] = m;
    __syncthreads();
    float mAll = sred[0];
#pragma unroll
    for (int i = 1; i < NWRP; i++) mAll = fmaxf(mAll, sred[i]);
    float e = (tid < P_) ? __expf(v - mAll) : 0.f;
    float s = e;
    for (int o = 16; o; o >>= 1) s += __shfl_xor_sync(~0u, s, o);
    __syncthreads();
    if (lane == 0) sred[wid] = s;
    __syncthreads();
    float sAll = sred[0];
#pragma unroll
    for (int i = 1; i < NWRP; i++) sAll += sred[i];
    float a = e / sAll;
    if (tid < P_) {
        g_alpha[b * P_ + tid] = a;
        alphas_out[((size_t)t * B_ + b) * P_ + tid] = a;
    }
    // beta
    float acc = (tid < P_) ? a * g_tC2pre[(t * B_ + b) * P_ + tid] : 0.f;
    for (int o = 16; o; o >>= 1) acc += __shfl_xor_sync(~0u, acc, o);
    __syncthreads();
    if (lane == 0) sred[wid] = acc;
    __syncthreads();
    if (tid == 0) {
        float sum = 0.f;
#pragma unroll
        for (int i = 0; i < NWRP; i++) sum += sred[i];
        g_beta[t * B_ + b] = sum + sc[196] + b_h21[0] + b_tC21[0] + temporalBias[0];
    }
    __syncthreads();
}

// ---------------- the single persistent kernel ----------------
__global__ void __launch_bounds__(NTHR, 1)
stdec_kernel(const float* __restrict__ videos,
             const float* __restrict__ h1in, const float* __restrict__ c1in,
             const float* __restrict__ h2in, const float* __restrict__ c2in,
             const float* __restrict__ spatialBias, const float* __restrict__ temporalBias,
             const float* __restrict__ W_h2p, const float* __restrict__ b_h2p,
             const float* __restrict__ W_sC21, const float* __restrict__ b_sC21,
             const float* __restrict__ W_h21, const float* __restrict__ b_h21,
             const float* __restrict__ W_tC21, const float* __restrict__ b_tC21,
             const float* __restrict__ Wih1, const float* __restrict__ Whh1,
             const float* __restrict__ bih1, const float* __restrict__ bhh1,
             const float* __restrict__ Wih2, const float* __restrict__ Whh2,
             const float* __restrict__ bih2, const float* __restrict__ bhh2,
             const float* __restrict__ W_fc, const float* __restrict__ b_fc,
             float* __restrict__ logits_out, float* __restrict__ alphas_out,
             float* __restrict__ betasT_out) {
    extern __shared__ __align__(1024) float dsm[];
    const int bid = blockIdx.x, tid = threadIdx.x;
    const int lane = tid & 31, wid = tid >> 5;
    const int gw = bid * NWRP + wid;

    unsigned barI = 0;
    unsigned gen0 = g_bar_gen;
    uint32_t smem_base = smem_u32(dsm);

    if (bid == 0 && tid == 0) g_aflag = 0;   // launch-reset (visible after first grid_sync)

    // ---- init states ----
    for (int idx = bid * NTHR + tid; idx < B_ * H_; idx += NBLK * NTHR) {
        int b = idx >> 10, h = idx & 1023;
        float v1 = h1in[h], v2 = h2in[h];
        __nv_bfloat16 t1 = __float2bfloat16(v1);
        g_h1hi[idx] = t1; g_h1lo[idx] = __float2bfloat16(v1 - __bfloat162float(t1));
        __nv_bfloat16 t2 = __float2bfloat16(v2);
        g_h2hi[idx] = t2; g_h2lo[idx] = __float2bfloat16(v2 - __bfloat162float(t2));
        g_h2n[idx] = v2;
        g_c1[h * 32 + b] = c1in[h];
        g_c2[h * 32 + b] = c2in[h];
    }

    // ---- weight repack (once per launch) ----
    {
        const size_t N1 = (size_t)4096 * 1536, N2 = (size_t)4096 * 2048;
        for (size_t idx = (size_t)(bid * NTHR + tid); idx < N1 + N2; idx += (size_t)NBLK * NTHR) {
            if (idx < N1) {
                int R = (int)(idx / 1536), k = (int)(idx % 1536);
                int r = R & 127, mm = R >> 7;
                int q = r >> 5, u = (mm << 5) + (r & 31);
                int orig = q * 1024 + u;
                float w = (k < 512) ? Wih1[(size_t)orig * 512 + k]
                                    : Whh1[(size_t)orig * 1024 + (k - 512)];
                __nv_bfloat16 hi = __float2bfloat16(w);
                g_W1hi[idx] = hi;
                g_W1lo[idx] = __float2bfloat16(w - __bfloat162float(hi));
            } else {
                size_t j = idx - N1;
                int R = (int)(j / 2048), k = (int)(j % 2048);
                int r = R & 127, mm = R >> 7;
                int q = r >> 5, u = (mm << 5) + (r & 31);
                int orig = q * 1024 + u;
                float w = (k < 1024) ? Wih2[(size_t)orig * 1024 + k]
                                     : Whh2[(size_t)orig * 1024 + (k - 1024)];
                __nv_bfloat16 hi = __float2bfloat16(w);
                g_W2hi[j] = hi;
                g_W2lo[j] = __float2bfloat16(w - __bfloat162float(hi));
            }
        }
    }

    // ---- precompute sA2pre / tC2pre (2 tasks per block) ----
    {
        float* ws = dsm;
        float* wt = dsm + C_;
        for (int i = tid; i < C_; i += NTHR) { ws[i] = W_sC21[i]; wt[i] = W_tC21[i]; }
        __syncthreads();
        float bs0 = b_sC21[0];
        int half = tid >> 8, p = tid & 255;
        for (int task = bid * 2 + half; task < B_ * T_; task += NBLK * 2) {
            int b = task / T_, t = task % T_;
            if (p < P_) {
                const float* vp = videos + ((size_t)(b * T_ + t) * C_) * P_ + p;
                float accs = 0.f, acct = 0.f;
#pragma unroll 8
                for (int c = 0; c < C_; c++) {
                    float v = vp[(size_t)c * P_];
                    accs += v * ws[c];
                    acct += v * wt[c];
                }
                int o = (t * B_ + b) * P_ + p;
                g_sA2pre[o] = accs + bs0 + spatialBias[p];
                g_tC2pre[o] = acct;
            }
        }
        __syncthreads();
    }
    grid_sync(barI, gen0);

    // ---- recurrence: 3 phases / 3 barriers per step ----
    for (int t = 0; t < T_; t++) {
        // P1: h-dependent gemm parts + attention; then cooperative Y after alpha flag
        if (bid < 64) {
            int m = bid & 31, s = bid >> 5;     // gemm1 slices 1,2: k [512,1024),[1024,1536)
            gemm_part<0>(m, 512 + s * 512, 512, g_p1[1 + s] + m * 4096, dsm, smem_base);
        } else if (bid < 128) {
            int m = (bid - 64) & 31, s = (bid - 64) >> 5;  // gemm2 slices 1,2
            gemm_part<1>(m, 1024 + s * 512, 512, g_p2[1 + s] + m * 4096, dsm, smem_base);
        } else {
            for (int b = bid - 128; b < B_; b += 20)
                attn_b(t, b, dsm, W_h2p, b_h2p, W_h21, b_h21, b_tC21, temporalBias, alphas_out);
            __syncthreads();
            if (tid == 0) { __threadfence(); atomicAdd((unsigned*)&g_aflag, 1u); }
        }
        // wait for all 20 attention blocks, then all blocks do Y
        {
            if (tid == 0) {
                unsigned tgt = 20u * (unsigned)(t + 1);
                while (g_aflag < tgt) __nanosleep(32);
            }
            __syncthreads();
            __threadfence();
            for (int task = gw; task < B_ * C_; task += NBLK * NWRP) {
                int b = task >> 9, c = task & 511;
                const float* vp = videos + (((size_t)b * T_ + t) * C_ + c) * P_;
                const float* al = g_alpha + b * P_;
                float acc = 0.f;
                for (int p = lane; p < P_; p += 32) acc += al[p] * vp[p];
                for (int o = 16; o; o >>= 1) acc += __shfl_xor_sync(~0u, acc, o);
                if (lane == 0) {
                    __nv_bfloat16 hy = __float2bfloat16(acc);
                    g_Yhi[b * C_ + c] = hy;
                    g_Ylo[b * C_ + c] = __float2bfloat16(acc - __bfloat162float(hy));
                }
            }
        }
        grid_sync(barI, gen0);

        // P3: gemm1 Y-part (32 blocks, 512 k) + fused cell1
        if (bid < 32) {
            gemm_part<0>(bid, 0, 512, g_p1[0] + bid * 4096, dsm, smem_base);
            __syncthreads();
            cell_m<0>(t, bih1, bhh1);
        }
        grid_sync(barI, gen0);

        // P4: gemm2 h1'-part (32 blocks, 1024 k) + fused cell2
        if (bid < 32) {
            gemm_part<1>(bid, 0, 1024, g_p2[0] + bid * 4096, dsm, smem_base);
            __syncthreads();
            cell_m<1>(t, bih2, bhh2);
        }
        grid_sync(barI, gen0);
    }

    // ---- betas softmax over time ----
    if (bid == 0 && tid < B_) {
        int b = tid;
        float v[T_];
        float m = -1e30f;
#pragma unroll
        for (int t = 0; t < T_; t++) { v[t] = g_beta[t * B_ + b]; m = fmaxf(m, v[t]); }
        float s = 0.f;
#pragma unroll
        for (int t = 0; t < T_; t++) { v[t] = __expf(v[t] - m); s += v[t]; }
        float inv = 1.f / s;
#pragma unroll
        for (int t = 0; t < T_; t++) {
            float bt = v[t] * inv;
            g_betasT[b * T_ + t] = bt;
            betasT_out[b * T_ + t] = bt;
        }
    }
    grid_sync(barI, gen0);

    // ---- hbar ----
    for (int idx = bid * NTHR + tid; idx < H_ * B_; idx += NBLK * NTHR) {
        int h = idx >> 5, b = idx & 31;
        float acc = 0.f;
#pragma unroll
        for (int t = 0; t < T_; t++)
            acc += g_betasT[b * T_ + t] * g_h2hist[(size_t)t * H_ * B_ + h * B_ + b];
        g_hbarN[b * H_ + h] = acc;
    }
    grid_sync(barI, gen0);

    // ---- logits ----
    for (int task = gw; task < NC_ * B_; task += NBLK * NWRP) {
        int nc = task / B_, b = task % B_;
        const float4* wr = (const float4*)(W_fc + (size_t)nc * H_);
        const float4* xr = (const float4*)(g_hbarN + (size_t)b * H_);
        float acc = 0.f;
#pragma unroll
        for (int j = 0; j < 8; j++) acc += d4(wr[lane + 32 * j], xr[lane + 32 * j]);
        for (int o = 16; o; o >>= 1) acc += __shfl_xor_sync(~0u, acc, o);
        if (lane == 0) logits_out[b * NC_ + nc] = acc + b_fc[nc];
    }
}

// ---------------- launch ----------------
extern "C" void kernel_launch(void* const* d_in, const int* in_sizes, int n_in,
                              void* d_out, int out_size) {
    const float* videos       = (const float*)d_in[0];
    const float* h1           = (const float*)d_in[1];
    const float* c1           = (const float*)d_in[2];
    const float* h2           = (const float*)d_in[3];
    const float* c2           = (const float*)d_in[4];
    const float* spatialBias  = (const float*)d_in[5];
    const float* temporalBias = (const float*)d_in[6];
    const float* W_h2p        = (const float*)d_in[7];
    const float* b_h2p        = (const float*)d_in[8];
    const float* W_sC21       = (const float*)d_in[9];
    const float* b_sC21       = (const float*)d_in[10];
    const float* W_h21        = (const float*)d_in[11];
    const float* b_h21        = (const float*)d_in[12];
    const float* W_tC21       = (const float*)d_in[13];
    const float* b_tC21       = (const float*)d_in[14];
    const float* Wih1         = (const float*)d_in[15];
    const float* Whh1         = (const float*)d_in[16];
    const float* bih1         = (const float*)d_in[17];
    const float* bhh1         = (const float*)d_in[18];
    const float* Wih2         = (const float*)d_in[19];
    const float* Whh2         = (const float*)d_in[20];
    const float* bih2         = (const float*)d_in[21];
    const float* bhh2         = (const float*)d_in[22];
    const float* W_fc         = (const float*)d_in[23];
    const float* b_fc         = (const float*)d_in[24];

    float* out        = (float*)d_out;
    float* logits_out = out;
    float* alphas_out = out + B_ * NC_;
    float* betasT_out = out + B_ * NC_ + (size_t)T_ * B_ * P_;

    cudaFuncSetAttribute(stdec_kernel, cudaFuncAttributeMaxDynamicSharedMemorySize, SMEM_BYTES);
    stdec_kernel<<<NBLK, NTHR, SMEM_BYTES>>>(videos, h1, c1, h2, c2, spatialBias, temporalBias,
                                 W_h2p, b_h2p, W_sC21, b_sC21, W_h21, b_h21, W_tC21, b_tC21,
                                 Wih1, Whh1, bih1, bhh1, Wih2, Whh2, bih2, bhh2,
                                 W_fc, b_fc, logits_out, alphas_out, betasT_out);
}

// round 15
// speedup vs baseline: 1.2948x; 1.2948x over previous
#include <cuda_runtime.h>
#include <math.h>

#define B_  32
#define T_  20
#define C_  512
#define P_  196
#define H_  1024
#define NC_ 101
#define NBLK 148
#define NTHR 512
#define NWRP 16

// LSTM tiling: 16 k-groups (1 warp each), chunk = 16 k, triple-buffered
#define NGRP 16
#define CHK 16
#define XSTR 32                       // X tile row stride: [16 k][32 b]
#define WSTR 20                       // W tile row stride: [32 rows][16 k pad 20]
#define XSZ (CHK * XSTR)              // 512
#define WSZ (32 * WSTR)               // 640
#define GRPSZ (XSZ + WSZ)             // 1152
#define NBUF 3
#define SMEM_FLOATS (NBUF * NGRP * GRPSZ)   // 55296 floats = 221184 B
#define SMEM_BYTES (SMEM_FLOATS * 4)

// ---------------- device scratch ----------------
__device__ float g_sA2pre[T_ * B_ * P_];
__device__ float g_tC2pre[T_ * B_ * P_];
__device__ float g_sc[B_ * P_];
__device__ float g_betaH[B_];
__device__ float g_YT[C_ * B_];           // [c][b]
__device__ float g_h1T[2][H_ * B_];       // [h][b] double-buffered by step parity
__device__ float g_h2T[2][H_ * B_];
__device__ float g_h2n[B_ * H_];          // [b][h] copy for attention dots
__device__ float g_h2hist[T_ * H_ * B_];
__device__ float g_c1[H_ * B_];
__device__ float g_c2[H_ * B_];
__device__ float g_beta[T_ * B_];
__device__ float g_betasT[B_ * T_];
__device__ float g_hbarN[B_ * H_];
__device__ unsigned g_cnt2[32 * 32];      // 32 padded arrival counters (self-resetting)
__device__ volatile unsigned g_bar_gen;

__device__ __forceinline__ float sigm(float x) { return 1.0f / (1.0f + __expf(-x)); }
__device__ __forceinline__ float ftanh(float x) { return 1.0f - 2.0f / (__expf(2.0f * x) + 1.0f); }
__device__ __forceinline__ float d4(float4 a, float4 b) {
    return a.x * b.x + a.y * b.y + a.z * b.z + a.w * b.w;
}

// packed fp32x2
__device__ __forceinline__ unsigned long long splat2(float w) {
    unsigned long long d; unsigned u = __float_as_uint(w);
    asm("mov.b64 %0, {%1, %1};" : "=l"(d) : "r"(u));
    return d;
}
__device__ __forceinline__ unsigned long long fma2(unsigned long long a, unsigned long long b,
                                                   unsigned long long c) {
    unsigned long long d;
    asm("fma.rn.f32x2 %0, %1, %2, %3;" : "=l"(d) : "l"(a), "l"(b), "l"(c));
    return d;
}

__device__ __forceinline__ void cp16(float* dst, const float* src) {
    unsigned u = (unsigned)__cvta_generic_to_shared(dst);
    asm volatile("cp.async.cg.shared.global [%0], [%1], 16;" :: "r"(u), "l"(src));
}
__device__ __forceinline__ void cp_commit() { asm volatile("cp.async.commit_group;" ::: "memory"); }
__device__ __forceinline__ void cp_wait2()  { asm volatile("cp.async.wait_group 2;" ::: "memory"); }
__device__ __forceinline__ void cp_wait1()  { asm volatile("cp.async.wait_group 1;" ::: "memory"); }
__device__ __forceinline__ void cp_wait0()  { asm volatile("cp.async.wait_group 0;" ::: "memory"); }

// distributed grid barrier: 32 counters; block0 warp detects + resets + releases.
__device__ __forceinline__ void grid_sync(unsigned& barI, unsigned gen0) {
    barI++;
    __syncthreads();
    const int tid = threadIdx.x, bid = blockIdx.x;
    if (tid == 0) { __threadfence(); atomicAdd(&g_cnt2[(bid & 31) * 32], 1u); }
    if (bid == 0 && tid < 32) {
        unsigned nj = (tid < 20) ? 5u : 4u;
        volatile unsigned* c = &g_cnt2[tid * 32];
        while (*c < nj) __nanosleep(32);
        atomicSub(&g_cnt2[tid * 32], nj);
        __syncwarp(0xffffffffu);
        if (tid == 0) { __threadfence(); g_bar_gen = gen0 + barI; }
    } else if (tid == 0) {
        while ((unsigned)(g_bar_gen - gen0) < barI) __nanosleep(32);
    }
    __threadfence();
    __syncthreads();
}

// ---------------- LSTM: warp-autonomous 3-deep pipelined GEMM + fused cell ----------
// 128 blocks; block: 8 h-units (32 gate-rows) x 32 batch. 16 warps = 16 k-slices.
// Thread tile: 4 rows (trow+8i) x 8 batches (tx*8..+7) — splat amortized over 4 fma2.
template <int MODE>
__device__ void lstm_phase(int t,
                           const float* __restrict__ Wih, const float* __restrict__ Whh,
                           const float* __restrict__ bih, const float* __restrict__ bhh,
                           float* dsm) {
    constexpr int K1 = (MODE == 0) ? C_ : H_;
    constexpr int K = K1 + H_;
    constexpr int KG = K / NGRP;     // 96 or 128
    constexpr int NCH = KG / CHK;    // 6 or 8
    const int bid = blockIdx.x, tid = threadIdx.x;
    if (bid >= 128) return;
    const float* __restrict__ X1 = (MODE == 0) ? g_YT : g_h1T[(t + 1) & 1];
    const float* __restrict__ X2 = (MODE == 0) ? g_h1T[t & 1] : g_h2T[t & 1];

    const int h0 = bid * 8;
    const int g = tid >> 5;          // warp = k-group 0..15
    const int lane = tid & 31;
    const int trow = lane & 7;       // rows trow + 8*i, i=0..3
    const int tx = lane >> 3;        // batch oct: b = tx*8 .. tx*8+7

    unsigned long long acc[4][4];
#pragma unroll
    for (int i = 0; i < 4; i++)
#pragma unroll
        for (int j = 0; j < 4; j++) acc[i][j] = 0ull;

    auto load_chunk = [&](int c) {
        float* Xp = dsm + (c % NBUF) * (NGRP * GRPSZ) + g * GRPSZ;
        float* Wp = Xp + XSZ;
        const int kbase = g * KG + c * CHK;
#pragma unroll
        for (int i = 0; i < 4; i++) {               // X: [16 k][32 b]
            int f = lane + 32 * i;
            int kk = f >> 3, bq = f & 7;
            int kg2 = kbase + kk;
            const float* src = (kg2 < K1) ? (X1 + kg2 * B_ + bq * 4)
                                          : (X2 + (kg2 - K1) * B_ + bq * 4);
            cp16(Xp + kk * XSTR + bq * 4, src);
        }
#pragma unroll
        for (int i = 0; i < 4; i++) {               // W: [32 rows][16 k]
            int f = lane + 32 * i;
            int row = f >> 2, kq = f & 3;
            int kg2 = kbase + kq * 4;
            int grow = (row >> 3) * H_ + h0 + (row & 7);
            const float* src = (kg2 < K1) ? (Wih + (size_t)grow * K1 + kg2)
                                          : (Whh + (size_t)grow * H_ + (kg2 - K1));
            cp16(Wp + row * WSTR + kq * 4, src);
        }
    };

    load_chunk(0); cp_commit();
    load_chunk(1); cp_commit();

    for (int c = 0; c < NCH; c++) {
        if (c + 2 < NCH)      { load_chunk(c + 2); cp_commit(); cp_wait2(); }
        else if (c + 1 < NCH) { cp_wait1(); }
        else                  { cp_wait0(); }

        const float* Xp = dsm + (c % NBUF) * (NGRP * GRPSZ) + g * GRPSZ;
        const float* Wp = Xp + XSZ;
#pragma unroll
        for (int kk = 0; kk < CHK; kk += 4) {
            float4 wq[4];
            ulonglong2 xlo[4], xhi[4];
#pragma unroll
            for (int i = 0; i < 4; i++)
                wq[i] = *(const float4*)&Wp[(trow + 8 * i) * WSTR + kk];
#pragma unroll
            for (int r = 0; r < 4; r++) {
                xlo[r] = *(const ulonglong2*)&Xp[(kk + r) * XSTR + tx * 8];
                xhi[r] = *(const ulonglong2*)&Xp[(kk + r) * XSTR + tx * 8 + 4];
            }
#pragma unroll
            for (int r = 0; r < 4; r++) {
#pragma unroll
                for (int i = 0; i < 4; i++) {
                    unsigned long long w2 = splat2(((const float*)&wq[i])[r]);
                    acc[i][0] = fma2(w2, xlo[r].x, acc[i][0]);
                    acc[i][1] = fma2(w2, xlo[r].y, acc[i][1]);
                    acc[i][2] = fma2(w2, xhi[r].x, acc[i][2]);
                    acc[i][3] = fma2(w2, xhi[r].y, acc[i][3]);
                }
            }
        }
    }

    // all warps done with buffers -> alias Gs over them
    __syncthreads();
    float* Gs = dsm;  // [16 g][32 rows][32 b]
#pragma unroll
    for (int i = 0; i < 4; i++) {
        ulonglong2 u0; u0.x = acc[i][0]; u0.y = acc[i][1];
        ulonglong2 u1; u1.x = acc[i][2]; u1.y = acc[i][3];
        *(ulonglong2*)&Gs[g * 1024 + (trow + 8 * i) * 32 + tx * 8]     = u0;
        *(ulonglong2*)&Gs[g * 1024 + (trow + 8 * i) * 32 + tx * 8 + 4] = u1;
    }
    __syncthreads();

    if (tid < 256) {
        int u = tid >> 5, b = tid & 31;
        float gate[4];
#pragma unroll
        for (int q = 0; q < 4; q++) {
            int l = q * 8 + u;
            int row = q * H_ + h0 + u;
            float s = bih[row] + bhh[row];
#pragma unroll
            for (int gg = 0; gg < NGRP; gg++) s += Gs[gg * 1024 + l * 32 + b];
            gate[q] = s;
        }
        float i_ = sigm(gate[0]), f_ = sigm(gate[1]), gv = ftanh(gate[2]), o_ = sigm(gate[3]);
        float* cS = (MODE == 0) ? g_c1 : g_c2;
        int hb = (h0 + u) * B_ + b;
        float cn = f_ * cS[hb] + i_ * gv;
        float hn = o_ * ftanh(cn);
        cS[hb] = cn;
        if (MODE == 0) {
            g_h1T[(t + 1) & 1][hb] = hn;
        } else {
            g_h2T[(t + 1) & 1][hb] = hn;
            g_h2n[b * H_ + h0 + u] = hn;
            g_h2hist[(size_t)t * H_ * B_ + hb] = hn;
        }
    }
    __syncthreads();
}

// ---------------- the single persistent kernel ----------------
__global__ void __launch_bounds__(NTHR, 1)
stdec_kernel(const float* __restrict__ videos,
             const float* __restrict__ h1in, const float* __restrict__ c1in,
             const float* __restrict__ h2in, const float* __restrict__ c2in,
             const float* __restrict__ spatialBias, const float* __restrict__ temporalBias,
             const float* __restrict__ W_h2p, const float* __restrict__ b_h2p,
             const float* __restrict__ W_sC21, const float* __restrict__ b_sC21,
             const float* __restrict__ W_h21, const float* __restrict__ b_h21,
             const float* __restrict__ W_tC21, const float* __restrict__ b_tC21,
             const float* __restrict__ Wih1, const float* __restrict__ Whh1,
             const float* __restrict__ bih1, const float* __restrict__ bhh1,
             const float* __restrict__ Wih2, const float* __restrict__ Whh2,
             const float* __restrict__ bih2, const float* __restrict__ bhh2,
             const float* __restrict__ W_fc, const float* __restrict__ b_fc,
             float* __restrict__ logits_out, float* __restrict__ alphas_out,
             float* __restrict__ betasT_out) {
    extern __shared__ __align__(16) float dsm[];
    const int bid = blockIdx.x, tid = threadIdx.x;
    const int lane = tid & 31, wid = tid >> 5;
    const int gw = bid * NWRP + wid;

    unsigned barI = 0;
    unsigned gen0 = g_bar_gen;

    // ---- init states ----
    for (int idx = bid * NTHR + tid; idx < H_ * B_; idx += NBLK * NTHR) {
        int h = idx >> 5, b = idx & 31;
        g_h1T[0][idx] = h1in[h];
        g_h2T[0][idx] = h2in[h];
        g_c1[idx] = c1in[h];
        g_c2[idx] = c2in[h];
        g_h2n[b * H_ + h] = h2in[h];
    }

    // ---- precompute sA2pre / tC2pre (2 tasks per block) ----
    {
        float* ws = dsm;
        float* wt = dsm + C_;
        for (int i = tid; i < C_; i += NTHR) { ws[i] = W_sC21[i]; wt[i] = W_tC21[i]; }
        __syncthreads();
        float bs0 = b_sC21[0];
        int half = tid >> 8, p = tid & 255;
        for (int task = bid * 2 + half; task < B_ * T_; task += NBLK * 2) {
            int b = task / T_, t = task % T_;
            if (p < P_) {
                const float* vp = videos + ((size_t)(b * T_ + t) * C_) * P_ + p;
                float accs = 0.f, acct = 0.f;
#pragma unroll 8
                for (int c = 0; c < C_; c++) {
                    float v = vp[(size_t)c * P_];
                    accs += v * ws[c];
                    acct += v * wt[c];
                }
                int o = (t * B_ + b) * P_ + p;
                g_sA2pre[o] = accs + bs0 + spatialBias[p];
                g_tC2pre[o] = acct;
            }
        }
        __syncthreads();
    }
    grid_sync(barI, gen0);

    // ---- recurrence: 4 phases / 4 barriers per step ----
    for (int t = 0; t < T_; t++) {
        // phase 1: scores, warp per (b,p) dot over all blocks; p==196 -> betaH
        for (int task = gw; task < B_ * 197; task += NBLK * NWRP) {
            int b = task / 197, p = task % 197;
            const float4* xr = (const float4*)(g_h2n + b * H_);
            const float4* wr = (const float4*)((p < P_) ? (W_h2p + (size_t)p * H_) : W_h21);
            float acc = 0.f;
#pragma unroll
            for (int j = 0; j < 8; j++) acc += d4(wr[lane + 32 * j], xr[lane + 32 * j]);
            for (int o = 16; o; o >>= 1) acc += __shfl_xor_sync(~0u, acc, o);
            if (lane == 0) {
                if (p < P_)
                    g_sc[b * P_ + p] = acc + b_h2p[p] + g_sA2pre[(t * B_ + b) * P_ + p];
                else
                    g_betaH[b] = acc;
            }
        }
        grid_sync(barI, gen0);

        // phase 2: softmax + alpha/beta out + Y (blocks 0..127: b = bid>>2, chunk = bid&3)
        if (bid < 128) {
            float* sred = dsm;          // [16]
            float* s_alpha = dsm + 16;  // [196]
            int b = bid >> 2, chunk = bid & 3, c0 = chunk * 128;

            float v = (tid < P_) ? g_sc[b * P_ + tid] : -1e30f;
            float m = v;
            for (int o = 16; o; o >>= 1) m = fmaxf(m, __shfl_xor_sync(~0u, m, o));
            if (lane == 0) sred[wid] = m;
            __syncthreads();
            float mAll = sred[0];
#pragma unroll
            for (int i = 1; i < NWRP; i++) mAll = fmaxf(mAll, sred[i]);
            float e = (tid < P_) ? __expf(v - mAll) : 0.f;
            float s = e;
            for (int o = 16; o; o >>= 1) s += __shfl_xor_sync(~0u, s, o);
            __syncthreads();
            if (lane == 0) sred[wid] = s;
            __syncthreads();
            float sAll = sred[0];
#pragma unroll
            for (int i = 1; i < NWRP; i++) sAll += sred[i];
            float a = e / sAll;
            __syncthreads();
            if (tid < P_) {
                s_alpha[tid] = a;
                if (chunk == 0) alphas_out[((size_t)t * B_ + b) * P_ + tid] = a;
            }
            __syncthreads();

            if (chunk == 0) {
                float acc = (tid < P_) ? a * g_tC2pre[(t * B_ + b) * P_ + tid] : 0.f;
                for (int o = 16; o; o >>= 1) acc += __shfl_xor_sync(~0u, acc, o);
                if (lane == 0) sred[wid] = acc;
                __syncthreads();
                if (tid == 0) {
                    float sum = 0.f;
#pragma unroll
                    for (int i = 0; i < NWRP; i++) sum += sred[i];
                    g_beta[t * B_ + b] = sum + g_betaH[b] + b_h21[0] + b_tC21[0] + temporalBias[0];
                }
            }

            // Y: warp per c-row within this block's 128-c chunk
            for (int c = wid; c < 128; c += NWRP) {
                int cg = c0 + c;
                const float* vp = videos + (((size_t)b * T_ + t) * C_ + cg) * P_;
                float acc = 0.f;
                for (int p = lane; p < P_; p += 32) acc += s_alpha[p] * vp[p];
                for (int o = 16; o; o >>= 1) acc += __shfl_xor_sync(~0u, acc, o);
                if (lane == 0) g_YT[cg * B_ + b] = acc;
            }
        }
        grid_sync(barI, gen0);

        lstm_phase<0>(t, Wih1, Whh1, bih1, bhh1, dsm);
        grid_sync(barI, gen0);
        lstm_phase<1>(t, Wih2, Whh2, bih2, bhh2, dsm);
        grid_sync(barI, gen0);
    }

    // ---- betas softmax over time ----
    if (bid == 0 && tid < B_) {
        int b = tid;
        float v[T_];
        float m = -1e30f;
#pragma unroll
        for (int t = 0; t < T_; t++) { v[t] = g_beta[t * B_ + b]; m = fmaxf(m, v[t]); }
        float s = 0.f;
#pragma unroll
        for (int t = 0; t < T_; t++) { v[t] = __expf(v[t] - m); s += v[t]; }
        float inv = 1.f / s;
#pragma unroll
        for (int t = 0; t < T_; t++) {
            float bt = v[t] * inv;
            g_betasT[b * T_ + t] = bt;
            betasT_out[b * T_ + t] = bt;
        }
    }
    grid_sync(barI, gen0);

    // ---- hbar[b][h] = sum_t betasT[b][t] * h2hist[t][h][b] ----
    for (int idx = bid * NTHR + tid; idx < H_ * B_; idx += NBLK * NTHR) {
        int h = idx >> 5, b = idx & 31;
        float acc = 0.f;
#pragma unroll
        for (int t = 0; t < T_; t++)
            acc += g_betasT[b * T_ + t] * g_h2hist[(size_t)t * H_ * B_ + h * B_ + b];
        g_hbarN[b * H_ + h] = acc;
    }
    grid_sync(barI, gen0);

    // ---- logits: warp per (nc,b) dot over H ----
    for (int task = gw; task < NC_ * B_; task += NBLK * NWRP) {
        int nc = task / B_, b = task % B_;
        const float4* wr = (const float4*)(W_fc + (size_t)nc * H_);
        const float4* xr = (const float4*)(g_hbarN + (size_t)b * H_);
        float acc = 0.f;
#pragma unroll
        for (int j = 0; j < 8; j++) acc += d4(wr[lane + 32 * j], xr[lane + 32 * j]);
        for (int o = 16; o; o >>= 1) acc += __shfl_xor_sync(~0u, acc, o);
        if (lane == 0) logits_out[b * NC_ + nc] = acc + b_fc[nc];
    }
}

// ---------------- launch ----------------
extern "C" void kernel_launch(void* const* d_in, const int* in_sizes, int n_in,
                              void* d_out, int out_size) {
    const float* videos       = (const float*)d_in[0];
    const float* h1           = (const float*)d_in[1];
    const float* c1           = (const float*)d_in[2];
    const float* h2           = (const float*)d_in[3];
    const float* c2           = (const float*)d_in[4];
    const float* spatialBias  = (const float*)d_in[5];
    const float* temporalBias = (const float*)d_in[6];
    const float* W_h2p        = (const float*)d_in[7];
    const float* b_h2p        = (const float*)d_in[8];
    const float* W_sC21       = (const float*)d_in[9];
    const float* b_sC21       = (const float*)d_in[10];
    const float* W_h21        = (const float*)d_in[11];
    const float* b_h21        = (const float*)d_in[12];
    const float* W_tC21       = (const float*)d_in[13];
    const float* b_tC21       = (const float*)d_in[14];
    const float* Wih1         = (const float*)d_in[15];
    const float* Whh1         = (const float*)d_in[16];
    const float* bih1         = (const float*)d_in[17];
    const float* bhh1         = (const float*)d_in[18];
    const float* Wih2         = (const float*)d_in[19];
    const float* Whh2         = (const float*)d_in[20];
    const float* bih2         = (const float*)d_in[21];
    const float* bhh2         = (const float*)d_in[22];
    const float* W_fc         = (const float*)d_in[23];
    const float* b_fc         = (const float*)d_in[24];

    float* out        = (float*)d_out;
    float* logits_out = out;
    float* alphas_out = out + B_ * NC_;
    float* betasT_out = out + B_ * NC_ + (size_t)T_ * B_ * P_;

    cudaFuncSetAttribute(stdec_kernel, cudaFuncAttributeMaxDynamicSharedMemorySize, SMEM_BYTES);
    stdec_kernel<<<NBLK, NTHR, SMEM_BYTES>>>(videos, h1, c1, h2, c2, spatialBias, temporalBias,
                                 W_h2p, b_h2p, W_sC21, b_sC21, W_h21, b_h21, W_tC21, b_tC21,
                                 Wih1, Whh1, bih1, bhh1, Wih2, Whh2, bih2, bhh2,
                                 W_fc, b_fc, logits_out, alphas_out, betasT_out);
}

// round 16
// speedup vs baseline: 1.3519x; 1.0441x over previous
#include <cuda_runtime.h>
#include <math.h>

#define B_  32
#define T_  20
#define C_  512
#define P_  196
#define H_  1024
#define NC_ 101
#define NBLK 148
#define NTHR 512
#define NWRP 16

// LSTM tiling: 16 k-groups (1 warp each), chunk = 16 k, triple-buffered
#define NGRP 16
#define CHK 16
#define XSTR 32                       // X tile row stride: [16 k][32 b]
#define WSTR 20                       // W tile row stride: [32 rows][16 k pad 20]
#define XSZ (CHK * XSTR)              // 512
#define WSZ (32 * WSTR)               // 640
#define GRPSZ (XSZ + WSZ)             // 1152
#define NBUF 3
#define SMEM_FLOATS (NBUF * NGRP * GRPSZ)   // 55296 floats = 221184 B
#define SMEM_BYTES (SMEM_FLOATS * 4)

// ---------------- device scratch ----------------
__device__ float g_sA2pre[T_ * B_ * P_];
__device__ float g_tC2pre[T_ * B_ * P_];
__device__ float g_sc[B_ * 197];          // scores; slot 196 = h2.W_h21 (for beta)
__device__ float g_YT[C_ * B_];           // [c][b]
__device__ float g_h1T[2][H_ * B_];       // [h][b] double-buffered by step parity
__device__ float g_h2T[2][H_ * B_];
__device__ float g_h2n[B_ * H_];          // [b][h] copy for attention dots
__device__ float g_h2hist[T_ * H_ * B_];
__device__ float g_c1[H_ * B_];
__device__ float g_c2[H_ * B_];
__device__ float g_beta[T_ * B_];
__device__ float g_betasT[B_ * T_];
__device__ float g_hbarN[B_ * H_];
__device__ unsigned g_cnt2[32 * 32];      // grid-barrier arrival counters
__device__ volatile unsigned g_bar_gen;
__device__ unsigned g_bcnt[32 * 32];      // per-batch score-ready counters (monotonic)

__device__ __forceinline__ float sigm(float x) { return 1.0f / (1.0f + __expf(-x)); }
__device__ __forceinline__ float ftanh(float x) { return 1.0f - 2.0f / (__expf(2.0f * x) + 1.0f); }
__device__ __forceinline__ float d4(float4 a, float4 b) {
    return a.x * b.x + a.y * b.y + a.z * b.z + a.w * b.w;
}

// packed fp32x2
__device__ __forceinline__ unsigned long long splat2(float w) {
    unsigned long long d; unsigned u = __float_as_uint(w);
    asm("mov.b64 %0, {%1, %1};" : "=l"(d) : "r"(u));
    return d;
}
__device__ __forceinline__ unsigned long long fma2(unsigned long long a, unsigned long long b,
                                                   unsigned long long c) {
    unsigned long long d;
    asm("fma.rn.f32x2 %0, %1, %2, %3;" : "=l"(d) : "l"(a), "l"(b), "l"(c));
    return d;
}

__device__ __forceinline__ void cp16(float* dst, const float* src) {
    unsigned u = (unsigned)__cvta_generic_to_shared(dst);
    asm volatile("cp.async.cg.shared.global [%0], [%1], 16;" :: "r"(u), "l"(src));
}
__device__ __forceinline__ void cp_commit() { asm volatile("cp.async.commit_group;" ::: "memory"); }
__device__ __forceinline__ void cp_wait2()  { asm volatile("cp.async.wait_group 2;" ::: "memory"); }
__device__ __forceinline__ void cp_wait1()  { asm volatile("cp.async.wait_group 1;" ::: "memory"); }
__device__ __forceinline__ void cp_wait0()  { asm volatile("cp.async.wait_group 0;" ::: "memory"); }

// distributed grid barrier: 32 counters; block0 warp detects + resets + releases.
__device__ __forceinline__ void grid_sync(unsigned& barI, unsigned gen0) {
    barI++;
    __syncthreads();
    const int tid = threadIdx.x, bid = blockIdx.x;
    if (tid == 0) { __threadfence(); atomicAdd(&g_cnt2[(bid & 31) * 32], 1u); }
    if (bid == 0 && tid < 32) {
        unsigned nj = (tid < 20) ? 5u : 4u;
        volatile unsigned* c = &g_cnt2[tid * 32];
        while (*c < nj) __nanosleep(32);
        atomicSub(&g_cnt2[tid * 32], nj);
        __syncwarp(0xffffffffu);
        if (tid == 0) { __threadfence(); g_bar_gen = gen0 + barI; }
    } else if (tid == 0) {
        while ((unsigned)(g_bar_gen - gen0) < barI) __nanosleep(32);
    }
    __threadfence();
    __syncthreads();
}

// ---------------- LSTM: warp-autonomous 3-deep pipelined GEMM + fused cell ----------
// 128 blocks; block: 8 h-units (32 gate-rows) x 32 batch. 16 warps = 16 k-slices.
// Thread tile: 8 rows (trow+4i) x 4 batches (tx*4..+3)  [R9 geometry]
template <int MODE>
__device__ void lstm_phase(int t,
                           const float* __restrict__ Wih, const float* __restrict__ Whh,
                           const float* __restrict__ bih, const float* __restrict__ bhh,
                           float* dsm) {
    constexpr int K1 = (MODE == 0) ? C_ : H_;
    constexpr int K = K1 + H_;
    constexpr int KG = K / NGRP;     // 96 or 128
    constexpr int NCH = KG / CHK;    // 6 or 8
    const int bid = blockIdx.x, tid = threadIdx.x;
    if (bid >= 128) return;
    const float* __restrict__ X1 = (MODE == 0) ? g_YT : g_h1T[(t + 1) & 1];
    const float* __restrict__ X2 = (MODE == 0) ? g_h1T[t & 1] : g_h2T[t & 1];

    const int h0 = bid * 8;
    const int g = tid >> 5;          // warp = k-group 0..15
    const int lane = tid & 31;
    const int tx = lane & 7;         // batch quad: b = tx*4 .. tx*4+3
    const int trow = lane >> 3;      // rows trow + 4*i, i=0..7

    unsigned long long acc[8][2];
#pragma unroll
    for (int i = 0; i < 8; i++) { acc[i][0] = 0ull; acc[i][1] = 0ull; }

    auto load_chunk = [&](int c) {
        float* Xp = dsm + (c % NBUF) * (NGRP * GRPSZ) + g * GRPSZ;
        float* Wp = Xp + XSZ;
        const int kbase = g * KG + c * CHK;
#pragma unroll
        for (int i = 0; i < 4; i++) {               // X: [16 k][32 b]
            int f = lane + 32 * i;
            int kk = f >> 3, bq = f & 7;
            int kg2 = kbase + kk;
            const float* src = (kg2 < K1) ? (X1 + kg2 * B_ + bq * 4)
                                          : (X2 + (kg2 - K1) * B_ + bq * 4);
            cp16(Xp + kk * XSTR + bq * 4, src);
        }
#pragma unroll
        for (int i = 0; i < 4; i++) {               // W: [32 rows][16 k]
            int f = lane + 32 * i;
            int row = f >> 2, kq = f & 3;
            int kg2 = kbase + kq * 4;
            int grow = (row >> 3) * H_ + h0 + (row & 7);
            const float* src = (kg2 < K1) ? (Wih + (size_t)grow * K1 + kg2)
                                          : (Whh + (size_t)grow * H_ + (kg2 - K1));
            cp16(Wp + row * WSTR + kq * 4, src);
        }
    };

    load_chunk(0); cp_commit();
    load_chunk(1); cp_commit();

    for (int c = 0; c < NCH; c++) {
        if (c + 2 < NCH)      { load_chunk(c + 2); cp_commit(); cp_wait2(); }
        else if (c + 1 < NCH) { cp_wait1(); }
        else                  { cp_wait0(); }

        const float* Xp = dsm + (c % NBUF) * (NGRP * GRPSZ) + g * GRPSZ;
        const float* Wp = Xp + XSZ;
#pragma unroll
        for (int kk = 0; kk < CHK; kk += 4) {
            float4 wq[8];
            ulonglong2 xq[4];
#pragma unroll
            for (int i = 0; i < 8; i++)
                wq[i] = *(const float4*)&Wp[(trow + 4 * i) * WSTR + kk];
#pragma unroll
            for (int r = 0; r < 4; r++)
                xq[r] = *(const ulonglong2*)&Xp[(kk + r) * XSTR + tx * 4];
#pragma unroll
            for (int r = 0; r < 4; r++) {
#pragma unroll
                for (int i = 0; i < 8; i++) {
                    unsigned long long w2 = splat2(((const float*)&wq[i])[r]);
                    acc[i][0] = fma2(w2, xq[r].x, acc[i][0]);
                    acc[i][1] = fma2(w2, xq[r].y, acc[i][1]);
                }
            }
        }
    }

    // all warps done with buffers -> alias Gs over them
    __syncthreads();
    float* Gs = dsm;  // [16 g][32 rows][32 b]
#pragma unroll
    for (int i = 0; i < 8; i++) {
        ulonglong2 uv; uv.x = acc[i][0]; uv.y = acc[i][1];
        *(ulonglong2*)&Gs[g * 1024 + (trow + 4 * i) * 32 + tx * 4] = uv;
    }
    __syncthreads();

    if (tid < 256) {
        int u = tid >> 5, b = tid & 31;
        float gate[4];
#pragma unroll
        for (int q = 0; q < 4; q++) {
            int l = q * 8 + u;
            int row = q * H_ + h0 + u;
            float s = bih[row] + bhh[row];
#pragma unroll
            for (int gg = 0; gg < NGRP; gg++) s += Gs[gg * 1024 + l * 32 + b];
            gate[q] = s;
        }
        float i_ = sigm(gate[0]), f_ = sigm(gate[1]), gv = ftanh(gate[2]), o_ = sigm(gate[3]);
        float* cS = (MODE == 0) ? g_c1 : g_c2;
        int hb = (h0 + u) * B_ + b;
        float cn = f_ * cS[hb] + i_ * gv;
        float hn = o_ * ftanh(cn);
        cS[hb] = cn;
        if (MODE == 0) {
            g_h1T[(t + 1) & 1][hb] = hn;
        } else {
            g_h2T[(t + 1) & 1][hb] = hn;
            g_h2n[b * H_ + h0 + u] = hn;
            g_h2hist[(size_t)t * H_ * B_ + hb] = hn;
        }
    }
    __syncthreads();
}

// ---------------- the single persistent kernel ----------------
__global__ void __launch_bounds__(NTHR, 1)
stdec_kernel(const float* __restrict__ videos,
             const float* __restrict__ h1in, const float* __restrict__ c1in,
             const float* __restrict__ h2in, const float* __restrict__ c2in,
             const float* __restrict__ spatialBias, const float* __restrict__ temporalBias,
             const float* __restrict__ W_h2p, const float* __restrict__ b_h2p,
             const float* __restrict__ W_sC21, const float* __restrict__ b_sC21,
             const float* __restrict__ W_h21, const float* __restrict__ b_h21,
             const float* __restrict__ W_tC21, const float* __restrict__ b_tC21,
             const float* __restrict__ Wih1, const float* __restrict__ Whh1,
             const float* __restrict__ bih1, const float* __restrict__ bhh1,
             const float* __restrict__ Wih2, const float* __restrict__ Whh2,
             const float* __restrict__ bih2, const float* __restrict__ bhh2,
             const float* __restrict__ W_fc, const float* __restrict__ b_fc,
             float* __restrict__ logits_out, float* __restrict__ alphas_out,
             float* __restrict__ betasT_out) {
    extern __shared__ __align__(16) float dsm[];
    const int bid = blockIdx.x, tid = threadIdx.x;
    const int lane = tid & 31, wid = tid >> 5;
    const int gw = bid * NWRP + wid;

    unsigned barI = 0;
    unsigned gen0 = g_bar_gen;

    // launch-reset of per-batch counters (visible after first grid_sync)
    if (bid == 0 && tid < 32) g_bcnt[tid * 32] = 0u;

    // ---- init states ----
    for (int idx = bid * NTHR + tid; idx < H_ * B_; idx += NBLK * NTHR) {
        int h = idx >> 5, b = idx & 31;
        g_h1T[0][idx] = h1in[h];
        g_h2T[0][idx] = h2in[h];
        g_c1[idx] = c1in[h];
        g_c2[idx] = c2in[h];
        g_h2n[b * H_ + h] = h2in[h];
    }

    // ---- precompute sA2pre / tC2pre (2 tasks per block) ----
    {
        float* ws = dsm;
        float* wt = dsm + C_;
        for (int i = tid; i < C_; i += NTHR) { ws[i] = W_sC21[i]; wt[i] = W_tC21[i]; }
        __syncthreads();
        float bs0 = b_sC21[0];
        int half = tid >> 8, p = tid & 255;
        for (int task = bid * 2 + half; task < B_ * T_; task += NBLK * 2) {
            int b = task / T_, t = task % T_;
            if (p < P_) {
                const float* vp = videos + ((size_t)(b * T_ + t) * C_) * P_ + p;
                float accs = 0.f, acct = 0.f;
#pragma unroll 8
                for (int c = 0; c < C_; c++) {
                    float v = vp[(size_t)c * P_];
                    accs += v * ws[c];
                    acct += v * wt[c];
                }
                int o = (t * B_ + b) * P_ + p;
                g_sA2pre[o] = accs + bs0 + spatialBias[p];
                g_tC2pre[o] = acct;
            }
        }
        __syncthreads();
    }
    grid_sync(barI, gen0);

    // ---- recurrence: 3 grid barriers + 1 per-batch mini-barrier per step ----
    for (int t = 0; t < T_; t++) {
        // merged phase: scores (4 blocks per batch, strided p) -> mini-sync -> softmax+beta+Y
        if (bid < 128) {
            int b = bid >> 2, chunk = bid & 3, c0 = chunk * 128;

            // scores: this block handles p = chunk + 4*i
            for (int i = wid; chunk + 4 * i < 197; i += NWRP) {
                int p = chunk + 4 * i;
                const float4* xr = (const float4*)(g_h2n + b * H_);
                const float4* wr = (const float4*)((p < P_) ? (W_h2p + (size_t)p * H_) : W_h21);
                float acc = 0.f;
#pragma unroll
                for (int j = 0; j < 8; j++) acc += d4(wr[lane + 32 * j], xr[lane + 32 * j]);
                for (int o = 16; o; o >>= 1) acc += __shfl_xor_sync(~0u, acc, o);
                if (lane == 0)
                    g_sc[b * 197 + p] = (p < P_)
                        ? (acc + b_h2p[p] + g_sA2pre[(t * B_ + b) * P_ + p]) : acc;
            }
            __syncthreads();
            // per-batch mini-barrier: 4 producers
            if (tid == 0) {
                __threadfence();
                atomicAdd(&g_bcnt[b * 32], 1u);
                unsigned tgt = 4u * (unsigned)(t + 1);
                volatile unsigned* c = &g_bcnt[b * 32];
                while (*c < tgt) __nanosleep(32);
            }
            __syncthreads();
            __threadfence();

            float* sred = dsm;          // [16]
            float* s_alpha = dsm + 16;  // [196]

            float v = (tid < P_) ? g_sc[b * 197 + tid] : -1e30f;
            float m = v;
            for (int o = 16; o; o >>= 1) m = fmaxf(m, __shfl_xor_sync(~0u, m, o));
            if (lane == 0) sred[wid] = m;
            __syncthreads();
            float mAll = sred[0];
#pragma unroll
            for (int i = 1; i < NWRP; i++) mAll = fmaxf(mAll, sred[i]);
            float e = (tid < P_) ? __expf(v - mAll) : 0.f;
            float s = e;
            for (int o = 16; o; o >>= 1) s += __shfl_xor_sync(~0u, s, o);
            __syncthreads();
            if (lane == 0) sred[wid] = s;
            __syncthreads();
            float sAll = sred[0];
#pragma unroll
            for (int i = 1; i < NWRP; i++) sAll += sred[i];
            float a = e / sAll;
            __syncthreads();
            if (tid < P_) {
                s_alpha[tid] = a;
                if (chunk == 0) alphas_out[((size_t)t * B_ + b) * P_ + tid] = a;
            }
            __syncthreads();

            if (chunk == 0) {
                float acc = (tid < P_) ? a * g_tC2pre[(t * B_ + b) * P_ + tid] : 0.f;
                for (int o = 16; o; o >>= 1) acc += __shfl_xor_sync(~0u, acc, o);
                if (lane == 0) sred[wid] = acc;
                __syncthreads();
                if (tid == 0) {
                    float sum = 0.f;
#pragma unroll
                    for (int i = 0; i < NWRP; i++) sum += sred[i];
                    g_beta[t * B_ + b] = sum + g_sc[b * 197 + 196] + b_h21[0] + b_tC21[0] + temporalBias[0];
                }
            }

            // Y: warp per c-row within this block's 128-c chunk
            for (int c = wid; c < 128; c += NWRP) {
                int cg = c0 + c;
                const float* vp = videos + (((size_t)b * T_ + t) * C_ + cg) * P_;
                float acc = 0.f;
                for (int p = lane; p < P_; p += 32) acc += s_alpha[p] * vp[p];
                for (int o = 16; o; o >>= 1) acc += __shfl_xor_sync(~0u, acc, o);
                if (lane == 0) g_YT[cg * B_ + b] = acc;
            }
        }
        grid_sync(barI, gen0);

        lstm_phase<0>(t, Wih1, Whh1, bih1, bhh1, dsm);
        grid_sync(barI, gen0);
        lstm_phase<1>(t, Wih2, Whh2, bih2, bhh2, dsm);
        grid_sync(barI, gen0);
    }

    // ---- betas softmax over time ----
    if (bid == 0 && tid < B_) {
        int b = tid;
        float v[T_];
        float m = -1e30f;
#pragma unroll
        for (int t = 0; t < T_; t++) { v[t] = g_beta[t * B_ + b]; m = fmaxf(m, v[t]); }
        float s = 0.f;
#pragma unroll
        for (int t = 0; t < T_; t++) { v[t] = __expf(v[t] - m); s += v[t]; }
        float inv = 1.f / s;
#pragma unroll
        for (int t = 0; t < T_; t++) {
            float bt = v[t] * inv;
            g_betasT[b * T_ + t] = bt;
            betasT_out[b * T_ + t] = bt;
        }
    }
    grid_sync(barI, gen0);

    // ---- hbar[b][h] = sum_t betasT[b][t] * h2hist[t][h][b] ----
    for (int idx = bid * NTHR + tid; idx < H_ * B_; idx += NBLK * NTHR) {
        int h = idx >> 5, b = idx & 31;
        float acc = 0.f;
#pragma unroll
        for (int t = 0; t < T_; t++)
            acc += g_betasT[b * T_ + t] * g_h2hist[(size_t)t * H_ * B_ + h * B_ + b];
        g_hbarN[b * H_ + h] = acc;
    }
    grid_sync(barI, gen0);

    // ---- logits: warp per (nc,b) dot over H ----
    for (int task = gw; task < NC_ * B_; task += NBLK * NWRP) {
        int nc = task / B_, b = task % B_;
        const float4* wr = (const float4*)(W_fc + (size_t)nc * H_);
        const float4* xr = (const float4*)(g_hbarN + (size_t)b * H_);
        float acc = 0.f;
#pragma unroll
        for (int j = 0; j < 8; j++) acc += d4(wr[lane + 32 * j], xr[lane + 32 * j]);
        for (int o = 16; o; o >>= 1) acc += __shfl_xor_sync(~0u, acc, o);
        if (lane == 0) logits_out[b * NC_ + nc] = acc + b_fc[nc];
    }
}

// ---------------- launch ----------------
extern "C" void kernel_launch(void* const* d_in, const int* in_sizes, int n_in,
                              void* d_out, int out_size) {
    const float* videos       = (const float*)d_in[0];
    const float* h1           = (const float*)d_in[1];
    const float* c1           = (const float*)d_in[2];
    const float* h2           = (const float*)d_in[3];
    const float* c2           = (const float*)d_in[4];
    const float* spatialBias  = (const float*)d_in[5];
    const float* temporalBias = (const float*)d_in[6];
    const float* W_h2p        = (const float*)d_in[7];
    const float* b_h2p        = (const float*)d_in[8];
    const float* W_sC21       = (const float*)d_in[9];
    const float* b_sC21       = (const float*)d_in[10];
    const float* W_h21        = (const float*)d_in[11];
    const float* b_h21        = (const float*)d_in[12];
    const float* W_tC21       = (const float*)d_in[13];
    const float* b_tC21       = (const float*)d_in[14];
    const float* Wih1         = (const float*)d_in[15];
    const float* Whh1         = (const float*)d_in[16];
    const float* bih1         = (const float*)d_in[17];
    const float* bhh1         = (const float*)d_in[18];
    const float* Wih2         = (const float*)d_in[19];
    const float* Whh2         = (const float*)d_in[20];
    const float* bih2         = (const float*)d_in[21];
    const float* bhh2         = (const float*)d_in[22];
    const float* W_fc         = (const float*)d_in[23];
    const float* b_fc         = (const float*)d_in[24];

    float* out        = (float*)d_out;
    float* logits_out = out;
    float* alphas_out = out + B_ * NC_;
    float* betasT_out = out + B_ * NC_ + (size_t)T_ * B_ * P_;

    cudaFuncSetAttribute(stdec_kernel, cudaFuncAttributeMaxDynamicSharedMemorySize, SMEM_BYTES);
    stdec_kernel<<<NBLK, NTHR, SMEM_BYTES>>>(videos, h1, c1, h2, c2, spatialBias, temporalBias,
                                 W_h2p, b_h2p, W_sC21, b_sC21, W_h21, b_h21, W_tC21, b_tC21,
                                 Wih1, Whh1, bih1, bhh1, Wih2, Whh2, bih2, bhh2,
                                 W_fc, b_fc, logits_out, alphas_out, betasT_out);
}

// round 17
// speedup vs baseline: 1.3952x; 1.0320x over previous
#include <cuda_runtime.h>
#include <math.h>

#define B_  32
#define T_  20
#define C_  512
#define P_  196
#define H_  1024
#define NC_ 101
#define NBLK 148
#define NTHR 512
#define NWRP 16

// LSTM tiling: 16 k-groups (1 warp each), chunk = 16 k, triple-buffered
#define NGRP 16
#define CHK 16
#define XSTR 32                       // X tile row stride: [16 k][32 b]
#define WSTR 20                       // W tile row stride: [32 rows][16 k pad 20]
#define XSZ (CHK * XSTR)              // 512
#define WSZ (32 * WSTR)               // 640
#define GRPSZ (XSZ + WSZ)             // 1152
#define NBUF 3
#define SMEM_FLOATS (NBUF * NGRP * GRPSZ)   // 55296 floats = 221184 B
#define SMEM_BYTES (SMEM_FLOATS * 4)

// ---------------- device scratch ----------------
__device__ float g_sA2pre[T_ * B_ * P_];
__device__ float g_tC2pre[T_ * B_ * P_];
__device__ float g_sc[B_ * 197];          // scores; slot 196 = h2.W_h21 (for beta)
__device__ float g_YT[C_ * B_];           // [c][b]
__device__ float g_h1T[2][H_ * B_];       // [h][b] double-buffered by step parity
__device__ float g_h2T[2][H_ * B_];
__device__ float g_h2n[B_ * H_];          // [b][h] copy for attention dots
__device__ float g_h2hist[T_ * H_ * B_];
__device__ float g_c1[H_ * B_];
__device__ float g_c2[H_ * B_];
__device__ float g_beta[T_ * B_];
__device__ float g_betasT[B_ * T_];
__device__ float g_hbarN[B_ * H_];
__device__ unsigned g_cnt2[32 * 32];      // grid-barrier arrival counters
__device__ volatile unsigned g_bar_gen;
__device__ unsigned g_bcnt[32 * 32];      // per-batch score-ready counters (monotonic)

__device__ __forceinline__ float sigm(float x) { return 1.0f / (1.0f + __expf(-x)); }
__device__ __forceinline__ float ftanh(float x) { return 1.0f - 2.0f / (__expf(2.0f * x) + 1.0f); }
__device__ __forceinline__ float d4(float4 a, float4 b) {
    return a.x * b.x + a.y * b.y + a.z * b.z + a.w * b.w;
}

// packed fp32x2
__device__ __forceinline__ unsigned long long splat2(float w) {
    unsigned long long d; unsigned u = __float_as_uint(w);
    asm("mov.b64 %0, {%1, %1};" : "=l"(d) : "r"(u));
    return d;
}
__device__ __forceinline__ unsigned long long fma2(unsigned long long a, unsigned long long b,
                                                   unsigned long long c) {
    unsigned long long d;
    asm("fma.rn.f32x2 %0, %1, %2, %3;" : "=l"(d) : "l"(a), "l"(b), "l"(c));
    return d;
}

__device__ __forceinline__ void cp16(float* dst, const float* src) {
    unsigned u = (unsigned)__cvta_generic_to_shared(dst);
    asm volatile("cp.async.cg.shared.global [%0], [%1], 16;" :: "r"(u), "l"(src));
}
__device__ __forceinline__ void cp_commit() { asm volatile("cp.async.commit_group;" ::: "memory"); }
__device__ __forceinline__ void cp_wait2()  { asm volatile("cp.async.wait_group 2;" ::: "memory"); }
__device__ __forceinline__ void cp_wait1()  { asm volatile("cp.async.wait_group 1;" ::: "memory"); }
__device__ __forceinline__ void cp_wait0()  { asm volatile("cp.async.wait_group 0;" ::: "memory"); }

// distributed grid barrier: 32 counters; block0 warp detects + resets + releases.
__device__ __forceinline__ void grid_sync(unsigned& barI, unsigned gen0) {
    barI++;
    __syncthreads();
    const int tid = threadIdx.x, bid = blockIdx.x;
    if (tid == 0) { __threadfence(); atomicAdd(&g_cnt2[(bid & 31) * 32], 1u); }
    if (bid == 0 && tid < 32) {
        unsigned nj = (tid < 20) ? 5u : 4u;
        volatile unsigned* c = &g_cnt2[tid * 32];
        while (*c < nj) __nanosleep(32);
        atomicSub(&g_cnt2[tid * 32], nj);
        __syncwarp(0xffffffffu);
        if (tid == 0) { __threadfence(); g_bar_gen = gen0 + barI; }
    } else if (tid == 0) {
        while ((unsigned)(g_bar_gen - gen0) < barI) __nanosleep(32);
    }
    __threadfence();
    __syncthreads();
}

// ---------------- LSTM: warp-autonomous 3-deep pipelined GEMM + fused cell ----------
// 128 blocks; block: 8 h-units (32 gate-rows) x 32 batch. 16 warps = 16 k-slices.
// Thread tile: 8 rows (trow+4i) x 4 batches (tx*4..+3)  [R9 geometry]
template <int MODE>
__device__ void lstm_phase(int t,
                           const float* __restrict__ Wih, const float* __restrict__ Whh,
                           const float* __restrict__ bih, const float* __restrict__ bhh,
                           float* dsm) {
    constexpr int K1 = (MODE == 0) ? C_ : H_;
    constexpr int K = K1 + H_;
    constexpr int KG = K / NGRP;     // 96 or 128
    constexpr int NCH = KG / CHK;    // 6 or 8
    const int bid = blockIdx.x, tid = threadIdx.x;
    if (bid >= 128) return;
    const float* __restrict__ X1 = (MODE == 0) ? g_YT : g_h1T[(t + 1) & 1];
    const float* __restrict__ X2 = (MODE == 0) ? g_h1T[t & 1] : g_h2T[t & 1];

    const int h0 = bid * 8;
    const int g = tid >> 5;          // warp = k-group 0..15
    const int lane = tid & 31;
    const int tx = lane & 7;         // batch quad: b = tx*4 .. tx*4+3
    const int trow = lane >> 3;      // rows trow + 4*i, i=0..7

    unsigned long long acc[8][2];
#pragma unroll
    for (int i = 0; i < 8; i++) { acc[i][0] = 0ull; acc[i][1] = 0ull; }

    auto load_chunk = [&](int c) {
        float* Xp = dsm + (c % NBUF) * (NGRP * GRPSZ) + g * GRPSZ;
        float* Wp = Xp + XSZ;
        const int kbase = g * KG + c * CHK;
#pragma unroll
        for (int i = 0; i < 4; i++) {               // X: [16 k][32 b]
            int f = lane + 32 * i;
            int kk = f >> 3, bq = f & 7;
            int kg2 = kbase + kk;
            const float* src = (kg2 < K1) ? (X1 + kg2 * B_ + bq * 4)
                                          : (X2 + (kg2 - K1) * B_ + bq * 4);
            cp16(Xp + kk * XSTR + bq * 4, src);
        }
#pragma unroll
        for (int i = 0; i < 4; i++) {               // W: [32 rows][16 k]
            int f = lane + 32 * i;
            int row = f >> 2, kq = f & 3;
            int kg2 = kbase + kq * 4;
            int grow = (row >> 3) * H_ + h0 + (row & 7);
            const float* src = (kg2 < K1) ? (Wih + (size_t)grow * K1 + kg2)
                                          : (Whh + (size_t)grow * H_ + (kg2 - K1));
            cp16(Wp + row * WSTR + kq * 4, src);
        }
    };

    load_chunk(0); cp_commit();
    load_chunk(1); cp_commit();

    for (int c = 0; c < NCH; c++) {
        if (c + 2 < NCH)      { load_chunk(c + 2); cp_commit(); cp_wait2(); }
        else if (c + 1 < NCH) { cp_wait1(); }
        else                  { cp_wait0(); }

        const float* Xp = dsm + (c % NBUF) * (NGRP * GRPSZ) + g * GRPSZ;
        const float* Wp = Xp + XSZ;
#pragma unroll
        for (int kk = 0; kk < CHK; kk += 4) {
            float4 wq[8];
            ulonglong2 xq[4];
#pragma unroll
            for (int i = 0; i < 8; i++)
                wq[i] = *(const float4*)&Wp[(trow + 4 * i) * WSTR + kk];
#pragma unroll
            for (int r = 0; r < 4; r++)
                xq[r] = *(const ulonglong2*)&Xp[(kk + r) * XSTR + tx * 4];
#pragma unroll
            for (int r = 0; r < 4; r++) {
#pragma unroll
                for (int i = 0; i < 8; i++) {
                    unsigned long long w2 = splat2(((const float*)&wq[i])[r]);
                    acc[i][0] = fma2(w2, xq[r].x, acc[i][0]);
                    acc[i][1] = fma2(w2, xq[r].y, acc[i][1]);
                }
            }
        }
    }

    // all warps done with buffers -> alias Gs over them
    __syncthreads();
    float* Gs = dsm;  // [16 g][32 rows][32 b]
#pragma unroll
    for (int i = 0; i < 8; i++) {
        ulonglong2 uv; uv.x = acc[i][0]; uv.y = acc[i][1];
        *(ulonglong2*)&Gs[g * 1024 + (trow + 4 * i) * 32 + tx * 4] = uv;
    }
    __syncthreads();

    if (tid < 256) {
        int u = tid >> 5, b = tid & 31;
        float gate[4];
#pragma unroll
        for (int q = 0; q < 4; q++) {
            int l = q * 8 + u;
            int row = q * H_ + h0 + u;
            float s = bih[row] + bhh[row];
#pragma unroll
            for (int gg = 0; gg < NGRP; gg++) s += Gs[gg * 1024 + l * 32 + b];
            gate[q] = s;
        }
        float i_ = sigm(gate[0]), f_ = sigm(gate[1]), gv = ftanh(gate[2]), o_ = sigm(gate[3]);
        float* cS = (MODE == 0) ? g_c1 : g_c2;
        int hb = (h0 + u) * B_ + b;
        float cn = f_ * cS[hb] + i_ * gv;
        float hn = o_ * ftanh(cn);
        cS[hb] = cn;
        if (MODE == 0) {
            g_h1T[(t + 1) & 1][hb] = hn;
        } else {
            g_h2T[(t + 1) & 1][hb] = hn;
            g_h2n[b * H_ + h0 + u] = hn;
            g_h2hist[(size_t)t * H_ * B_ + hb] = hn;
        }
    }
    __syncthreads();
}

// ---------------- the single persistent kernel ----------------
__global__ void __launch_bounds__(NTHR, 1)
stdec_kernel(const float* __restrict__ videos,
             const float* __restrict__ h1in, const float* __restrict__ c1in,
             const float* __restrict__ h2in, const float* __restrict__ c2in,
             const float* __restrict__ spatialBias, const float* __restrict__ temporalBias,
             const float* __restrict__ W_h2p, const float* __restrict__ b_h2p,
             const float* __restrict__ W_sC21, const float* __restrict__ b_sC21,
             const float* __restrict__ W_h21, const float* __restrict__ b_h21,
             const float* __restrict__ W_tC21, const float* __restrict__ b_tC21,
             const float* __restrict__ Wih1, const float* __restrict__ Whh1,
             const float* __restrict__ bih1, const float* __restrict__ bhh1,
             const float* __restrict__ Wih2, const float* __restrict__ Whh2,
             const float* __restrict__ bih2, const float* __restrict__ bhh2,
             const float* __restrict__ W_fc, const float* __restrict__ b_fc,
             float* __restrict__ logits_out, float* __restrict__ alphas_out,
             float* __restrict__ betasT_out) {
    extern __shared__ __align__(16) float dsm[];
    const int bid = blockIdx.x, tid = threadIdx.x;
    const int lane = tid & 31, wid = tid >> 5;
    const int gw = bid * NWRP + wid;

    unsigned barI = 0;
    unsigned gen0 = g_bar_gen;

    // launch-reset of per-batch counters (visible after first grid_sync)
    if (bid == 0 && tid < 32) g_bcnt[tid * 32] = 0u;

    // ---- init states ----
    for (int idx = bid * NTHR + tid; idx < H_ * B_; idx += NBLK * NTHR) {
        int h = idx >> 5, b = idx & 31;
        g_h1T[0][idx] = h1in[h];
        g_h2T[0][idx] = h2in[h];
        g_c1[idx] = c1in[h];
        g_c2[idx] = c2in[h];
        g_h2n[b * H_ + h] = h2in[h];
    }

    // ---- precompute sA2pre / tC2pre (2 tasks per block); videos streamed evict-first ----
    {
        float* ws = dsm;
        float* wt = dsm + C_;
        for (int i = tid; i < C_; i += NTHR) { ws[i] = W_sC21[i]; wt[i] = W_tC21[i]; }
        __syncthreads();
        float bs0 = b_sC21[0];
        int half = tid >> 8, p = tid & 255;
        for (int task = bid * 2 + half; task < B_ * T_; task += NBLK * 2) {
            int b = task / T_, t = task % T_;
            if (p < P_) {
                const float* vp = videos + ((size_t)(b * T_ + t) * C_) * P_ + p;
                float accs = 0.f, acct = 0.f;
#pragma unroll 8
                for (int c = 0; c < C_; c++) {
                    float v = __ldcs(vp + (size_t)c * P_);
                    accs += v * ws[c];
                    acct += v * wt[c];
                }
                int o = (t * B_ + b) * P_ + p;
                g_sA2pre[o] = accs + bs0 + spatialBias[p];
                g_tC2pre[o] = acct;
            }
        }
        __syncthreads();
    }
    grid_sync(barI, gen0);

    // ---- recurrence: 3 grid barriers + 1 per-batch mini-barrier per step ----
    for (int t = 0; t < T_; t++) {
        // merged phase: scores (4 blocks per batch, strided p) -> mini-sync -> softmax+beta+Y
        if (bid < 128) {
            int b = bid >> 2, chunk = bid & 3, c0 = chunk * 128;

            // scores: this block handles p = chunk + 4*i
            for (int i = wid; chunk + 4 * i < 197; i += NWRP) {
                int p = chunk + 4 * i;
                const float4* xr = (const float4*)(g_h2n + b * H_);
                const float4* wr = (const float4*)((p < P_) ? (W_h2p + (size_t)p * H_) : W_h21);
                float acc = 0.f;
#pragma unroll
                for (int j = 0; j < 8; j++) acc += d4(wr[lane + 32 * j], xr[lane + 32 * j]);
                for (int o = 16; o; o >>= 1) acc += __shfl_xor_sync(~0u, acc, o);
                if (lane == 0)
                    g_sc[b * 197 + p] = (p < P_)
                        ? (acc + b_h2p[p] + g_sA2pre[(t * B_ + b) * P_ + p]) : acc;
            }
            __syncthreads();
            // per-batch mini-barrier: 4 producers
            if (tid == 0) {
                __threadfence();
                atomicAdd(&g_bcnt[b * 32], 1u);
                unsigned tgt = 4u * (unsigned)(t + 1);
                volatile unsigned* c = &g_bcnt[b * 32];
                while (*c < tgt) __nanosleep(32);
            }
            __syncthreads();
            __threadfence();

            float* sred = dsm;          // [16]
            float* s_alpha = dsm + 16;  // [196]

            float v = (tid < P_) ? g_sc[b * 197 + tid] : -1e30f;
            float m = v;
            for (int o = 16; o; o >>= 1) m = fmaxf(m, __shfl_xor_sync(~0u, m, o));
            if (lane == 0) sred[wid] = m;
            __syncthreads();
            float mAll = sred[0];
#pragma unroll
            for (int i = 1; i < NWRP; i++) mAll = fmaxf(mAll, sred[i]);
            float e = (tid < P_) ? __expf(v - mAll) : 0.f;
            float s = e;
            for (int o = 16; o; o >>= 1) s += __shfl_xor_sync(~0u, s, o);
            __syncthreads();
            if (lane == 0) sred[wid] = s;
            __syncthreads();
            float sAll = sred[0];
#pragma unroll
            for (int i = 1; i < NWRP; i++) sAll += sred[i];
            float a = e / sAll;
            __syncthreads();
            if (tid < P_) {
                s_alpha[tid] = a;
                if (chunk == 0) alphas_out[((size_t)t * B_ + b) * P_ + tid] = a;
            }
            __syncthreads();

            if (chunk == 0) {
                float acc = (tid < P_) ? a * g_tC2pre[(t * B_ + b) * P_ + tid] : 0.f;
                for (int o = 16; o; o >>= 1) acc += __shfl_xor_sync(~0u, acc, o);
                if (lane == 0) sred[wid] = acc;
                __syncthreads();
                if (tid == 0) {
                    float sum = 0.f;
#pragma unroll
                    for (int i = 0; i < NWRP; i++) sum += sred[i];
                    g_beta[t * B_ + b] = sum + g_sc[b * 197 + 196] + b_h21[0] + b_tC21[0] + temporalBias[0];
                }
            }

            // Y: warp per c-row; videos streamed evict-first (protect L2-resident weights)
            for (int c = wid; c < 128; c += NWRP) {
                int cg = c0 + c;
                const float* vp = videos + (((size_t)b * T_ + t) * C_ + cg) * P_;
                float acc = 0.f;
                for (int p = lane; p < P_; p += 32) acc += s_alpha[p] * __ldcs(vp + p);
                for (int o = 16; o; o >>= 1) acc += __shfl_xor_sync(~0u, acc, o);
                if (lane == 0) g_YT[cg * B_ + b] = acc;
            }
        }
        grid_sync(barI, gen0);

        lstm_phase<0>(t, Wih1, Whh1, bih1, bhh1, dsm);
        grid_sync(barI, gen0);
        lstm_phase<1>(t, Wih2, Whh2, bih2, bhh2, dsm);
        grid_sync(barI, gen0);
    }

    // ---- betas softmax over time ----
    if (bid == 0 && tid < B_) {
        int b = tid;
        float v[T_];
        float m = -1e30f;
#pragma unroll
        for (int t = 0; t < T_; t++) { v[t] = g_beta[t * B_ + b]; m = fmaxf(m, v[t]); }
        float s = 0.f;
#pragma unroll
        for (int t = 0; t < T_; t++) { v[t] = __expf(v[t] - m); s += v[t]; }
        float inv = 1.f / s;
#pragma unroll
        for (int t = 0; t < T_; t++) {
            float bt = v[t] * inv;
            g_betasT[b * T_ + t] = bt;
            betasT_out[b * T_ + t] = bt;
        }
    }
    grid_sync(barI, gen0);

    // ---- hbar[b][h] = sum_t betasT[b][t] * h2hist[t][h][b] ----
    for (int idx = bid * NTHR + tid; idx < H_ * B_; idx += NBLK * NTHR) {
        int h = idx >> 5, b = idx & 31;
        float acc = 0.f;
#pragma unroll
        for (int t = 0; t < T_; t++)
            acc += g_betasT[b * T_ + t] * g_h2hist[(size_t)t * H_ * B_ + h * B_ + b];
        g_hbarN[b * H_ + h] = acc;
    }
    grid_sync(barI, gen0);

    // ---- logits: warp per (nc,b) dot over H ----
    for (int task = gw; task < NC_ * B_; task += NBLK * NWRP) {
        int nc = task / B_, b = task % B_;
        const float4* wr = (const float4*)(W_fc + (size_t)nc * H_);
        const float4* xr = (const float4*)(g_hbarN + (size_t)b * H_);
        float acc = 0.f;
#pragma unroll
        for (int j = 0; j < 8; j++) acc += d4(wr[lane + 32 * j], xr[lane + 32 * j]);
        for (int o = 16; o; o >>= 1) acc += __shfl_xor_sync(~0u, acc, o);
        if (lane == 0) logits_out[b * NC_ + nc] = acc + b_fc[nc];
    }
}

// ---------------- launch ----------------
extern "C" void kernel_launch(void* const* d_in, const int* in_sizes, int n_in,
                              void* d_out, int out_size) {
    const float* videos       = (const float*)d_in[0];
    const float* h1           = (const float*)d_in[1];
    const float* c1           = (const float*)d_in[2];
    const float* h2           = (const float*)d_in[3];
    const float* c2           = (const float*)d_in[4];
    const float* spatialBias  = (const float*)d_in[5];
    const float* temporalBias = (const float*)d_in[6];
    const float* W_h2p        = (const float*)d_in[7];
    const float* b_h2p        = (const float*)d_in[8];
    const float* W_sC21       = (const float*)d_in[9];
    const float* b_sC21       = (const float*)d_in[10];
    const float* W_h21        = (const float*)d_in[11];
    const float* b_h21        = (const float*)d_in[12];
    const float* W_tC21       = (const float*)d_in[13];
    const float* b_tC21       = (const float*)d_in[14];
    const float* Wih1         = (const float*)d_in[15];
    const float* Whh1         = (const float*)d_in[16];
    const float* bih1         = (const float*)d_in[17];
    const float* bhh1         = (const float*)d_in[18];
    const float* Wih2         = (const float*)d_in[19];
    const float* Whh2         = (const float*)d_in[20];
    const float* bih2         = (const float*)d_in[21];
    const float* bhh2         = (const float*)d_in[22];
    const float* W_fc         = (const float*)d_in[23];
    const float* b_fc         = (const float*)d_in[24];

    float* out        = (float*)d_out;
    float* logits_out = out;
    float* alphas_out = out + B_ * NC_;
    float* betasT_out = out + B_ * NC_ + (size_t)T_ * B_ * P_;

    cudaFuncSetAttribute(stdec_kernel, cudaFuncAttributeMaxDynamicSharedMemorySize, SMEM_BYTES);
    stdec_kernel<<<NBLK, NTHR, SMEM_BYTES>>>(videos, h1, c1, h2, c2, spatialBias, temporalBias,
                                 W_h2p, b_h2p, W_sC21, b_sC21, W_h21, b_h21, W_tC21, b_tC21,
                                 Wih1, Whh1, bih1, bhh1, Wih2, Whh2, bih2, bhh2,
                                 W_fc, b_fc, logits_out, alphas_out, betasT_out);
}